// round 13
// baseline (speedup 1.0000x reference)
#include <cuda_runtime.h>
#include <cuda_fp16.h>
#include <math.h>
#include <stdint.h>

// ---------------------------------------------------------------------------
// Problem constants
// ---------------------------------------------------------------------------
#define NB    128
#define NI    784
#define NH    410
#define NO    10
#define TSMP  300
#define KLEN  64
#define THETA 10.0f

#define NHP   416               // a1t column stride (NH padded to 416)
#define KP    832               // NI padded to 13*64
#define KC    64                // K per chunk
#define NKC   13
#define MT    128               // M rows per CTA
#define GROWS (NB * TSMP)       // 38400
#define MTILES (GROWS / MT)     // 300 exact

// SRM alpha-kernel taps as float literals -> immediate-form FFMA.
__device__ constexpr float EPS[KLEN] = {
    0.0000000000f, 0.2459603111f, 0.4451081857f, 0.6041258122f,
    0.7288475202f, 0.8243606354f, 0.8950948186f, 0.9449011654f,
    0.9771222064f, 0.9946538264f, 1.0000000000f, 0.9953211600f,
    0.9824769037f, 0.9630636870f, 0.9384480644f, 0.9097959895f,
    0.8780986178f, 0.8441950164f, 0.8087921356f, 0.7724823532f,
    0.7357588823f, 0.6990292760f, 0.6626272664f, 0.6268231239f,
    0.5918327133f, 0.5578254003f, 0.5249309464f, 0.4932455146f,
    0.4628368866f, 0.4337489957f, 0.4060058497f, 0.3796149272f,
    0.3545701066f, 0.3308541851f, 0.3084410408f, 0.2872974963f,
    0.2673848822f, 0.2486603977f, 0.2310782389f, 0.2145905593f,
    0.1991482735f, 0.1847017280f, 0.1712012558f, 0.1585976196f,
    0.1468423867f, 0.1358882254f, 0.1256891229f, 0.1162005724f,
    0.1073797042f, 0.0991853624f, 0.0915781944f, 0.0845206424f,
    0.0779770014f, 0.0719133646f, 0.0662976344f, 0.0610994814f,
    0.0562902814f, 0.0518430787f, 0.0477325337f, 0.0439348398f,
    0.0404276820f, 0.0371901540f, 0.0342026963f, 0.0314470440f
};

// ---------------------------------------------------------------------------
// Device scratch (no allocation allowed)
// ---------------------------------------------------------------------------
__device__ __half g_whi[(size_t)NHP * KP];           // W1 fp16 high part
__device__ __half g_wlo[(size_t)NHP * KP];           // W1 fp16 low part
__device__ float  g_a1t[(size_t)GROWS * NHP];        // a1 in [g][o] layout
__device__ float  g_s1[(size_t)NB * NH * TSMP];      // hidden spikes fp32
__device__ float  g_a2p[(size_t)4 * NB * NO * TSMP]; // fc2 partial sums

// ---------------------------------------------------------------------------
// Helpers
// ---------------------------------------------------------------------------
__device__ __forceinline__ uint32_t smem_u32(const void* p) {
    uint32_t a;
    asm("{ .reg .u64 t; cvta.to.shared.u64 t, %1; cvt.u32.u64 %0, t; }"
        : "=r"(a) : "l"(p));
    return a;
}

__device__ __forceinline__ uint32_t sw128(uint32_t byte) {
    return byte ^ ((byte >> 3) & 0x70u);
}

__device__ __forceinline__ void cp_async16(uint32_t dst, const void* src) {
    asm volatile("cp.async.cg.shared.global [%0], [%1], 16;"
                 :: "r"(dst), "l"(src) : "memory");
}
__device__ __forceinline__ void cp_commit() {
    asm volatile("cp.async.commit_group;" ::: "memory");
}

#define LDSM_X4(r0, r1, r2, r3, addr) \
    asm volatile("ldmatrix.sync.aligned.m8n8.x4.shared.b16 {%0,%1,%2,%3}, [%4];" \
                 : "=r"(r0), "=r"(r1), "=r"(r2), "=r"(r3) : "r"(addr))

#define MMA16816(c, a, b0, b1) \
    asm volatile("mma.sync.aligned.m16n8k16.row.col.f32.f16.f16.f32 " \
                 "{%0,%1,%2,%3}, {%4,%5,%6,%7}, {%8,%9}, {%0,%1,%2,%3};" \
                 : "+f"((c)[0]), "+f"((c)[1]), "+f"((c)[2]), "+f"((c)[3]) \
                 : "r"((a)[0]), "r"((a)[1]), "r"((a)[2]), "r"((a)[3]), \
                   "r"(b0), "r"(b1))

// ---------------------------------------------------------------------------
// Kernel A: split W1 fp32 -> fp16 hi/lo, padded row-major [416][832]
// ---------------------------------------------------------------------------
#define SPLIT_BLOCKS ((NHP * KP + 255) / 256)

__global__ __launch_bounds__(256) void split_w_kernel(const float* __restrict__ W1) {
    int idx = blockIdx.x * 256 + threadIdx.x;
    if (idx >= NHP * KP) return;
    int o = idx / KP;
    int k = idx - o * KP;
    float w = (o < NH && k < NI) ? W1[o * NI + k] : 0.0f;
    __half hi = __float2half_rn(w);
    __half lo = __float2half_rn(w - __half2float(hi));
    g_whi[idx] = hi;
    g_wlo[idx] = lo;
}

// ---------------------------------------------------------------------------
// Kernel B: fused Poisson-encode + HMMA GEMM
//   D[g][o] = sum_i s0[g][i] * (Whi[o][i] + Wlo[o][i]),
//   s0 encoded on the fly into swizzled SMEM (idle-pipe work under MMAs).
// Grid (nt=4, mt=300); nt<3 -> 128-col tiles, nt==3 -> 32-col tail.
// ---------------------------------------------------------------------------
#define SA(buf)  ((buf) * 16384u)
#define SBH(buf) (32768u + (buf) * 16384u)
#define SBL(buf) (65536u + (buf) * 16384u)
#define SM_GEMM  98304

__global__ __launch_bounds__(256, 2) void gemm1_mma_kernel(
    const float* __restrict__ img, const float* __restrict__ ru) {
    extern __shared__ char smem[];
    const uint32_t sb = smem_u32(smem);

    const int tid  = threadIdx.x;
    const int lane = tid & 31;
    const int warp = tid >> 5;
    const int nt   = blockIdx.x;      // 0..3
    const int mt   = blockIdx.y;      // 0..299

    // ---- per-thread encode bases: 4 tasks, each (io8, t_loc) fixed ----
    int ebase[4];   // (n*NI)*TSMP + t  (element offset into ru, fits int)
    int ibase[4];   // n*NI            (element offset into img)
#pragma unroll
    for (int r = 0; r < 4; r++) {
        int task = warp + 8 * r;
        int t_loc = (task >> 3) * 32 + lane;
        int g = mt * MT + t_loc;
        int n = g / TSMP;
        int t = g - n * TSMP;
        ebase[r] = n * NI * TSMP + t;
        ibase[r] = n * NI;
    }

    auto encode = [&](int kc, int buf) {
        unsigned char* A = (unsigned char*)smem + SA(buf);
        const int i0 = kc * KC;
#pragma unroll
        for (int r = 0; r < 4; r++) {
            int task = warp + 8 * r;
            int io8 = task & 7;
            int t_loc = (task >> 3) * 32 + lane;
            unsigned v[4];
#pragma unroll
            for (int jj = 0; jj < 4; jj++) {
                unsigned pack = 0;
#pragma unroll
                for (int h = 0; h < 2; h++) {
                    int i = i0 + io8 * 8 + jj * 2 + h;
                    unsigned bit = 0;
                    if (i < NI) {
                        float rv = __ldg(&ru[(size_t)(ebase[r] + i * TSMP)]);
                        float im = __ldg(&img[ibase[r] + i]);
                        bit = (rv < im) ? 0x3C00u : 0u;
                    }
                    pack |= bit << (16 * h);
                }
                v[jj] = pack;
            }
            uint32_t byte = (uint32_t)t_loc * 128 + io8 * 16;
            *(uint4*)(A + sw128(byte)) = make_uint4(v[0], v[1], v[2], v[3]);
        }
    };

    const int lrow = tid >> 3;        // 0..31
    const int lj   = tid & 7;

    auto issueB = [&](int kc, int buf) {
        if (nt < 3) {
            const __half* srcH = g_whi + (size_t)(nt * 128) * KP + kc * KC;
            const __half* srcL = g_wlo + (size_t)(nt * 128) * KP + kc * KC;
#pragma unroll
            for (int it = 0; it < 4; it++) {
                int row = lrow + it * 32;
                uint32_t off = sw128((uint32_t)row * 128 + lj * 16);
                cp_async16(sb + SBH(buf) + off, srcH + (size_t)row * KP + lj * 8);
                cp_async16(sb + SBL(buf) + off, srcL + (size_t)row * KP + lj * 8);
            }
        } else {
            const __half* srcH = g_whi + (size_t)384 * KP + kc * KC;
            const __half* srcL = g_wlo + (size_t)384 * KP + kc * KC;
            int row = lrow;           // 0..31
            uint32_t off = sw128((uint32_t)row * 128 + lj * 16);
            cp_async16(sb + SBH(buf) + off, srcH + (size_t)row * KP + lj * 8);
            cp_async16(sb + SBL(buf) + off, srcL + (size_t)row * KP + lj * 8);
        }
        cp_commit();
    };

    const int lt = lane >> 3;
    const int lr = lane & 7;

    float acc[4][4][4];
#pragma unroll
    for (int i = 0; i < 4; i++)
#pragma unroll
        for (int j = 0; j < 4; j++)
#pragma unroll
            for (int q = 0; q < 4; q++) acc[i][j][q] = 0.0f;

    issueB(0, 0);
    encode(0, 0);

    if (nt < 3) {
        // ------------------ full 128-col tile path ------------------
        const int wm = warp >> 2;
        const int wn = warp & 3;
        const uint32_t a_row = (uint32_t)(wm * 64 + (lt & 1) * 8 + lr);
        const uint32_t a_col = (uint32_t)((lt >> 1) * 8);
        const uint32_t b_row = (uint32_t)(wn * 32 + (lt >> 1) * 8 + lr);
        const uint32_t b_col = (uint32_t)((lt & 1) * 8);

        for (int kc = 0; kc < NKC; kc++) {
            if (kc + 1 < NKC) issueB(kc + 1, (kc + 1) & 1);
            if (kc + 1 < NKC) {
                asm volatile("cp.async.wait_group 1;" ::: "memory");
            } else {
                asm volatile("cp.async.wait_group 0;" ::: "memory");
            }
            __syncthreads();

            const int buf = kc & 1;
            const uint32_t abase = sb + SA(buf);
            const uint32_t hbase = sb + SBH(buf);
            const uint32_t lbase = sb + SBL(buf);

#pragma unroll
            for (int ks = 0; ks < 4; ks++) {
                uint32_t a[4][4];
#pragma unroll
                for (int mi = 0; mi < 4; mi++) {
                    uint32_t byte = (a_row + mi * 16) * 128 + (ks * 16 + a_col) * 2;
                    LDSM_X4(a[mi][0], a[mi][1], a[mi][2], a[mi][3], abase + sw128(byte));
                }
                uint32_t bh[2][4], bl[2][4];
#pragma unroll
                for (int nj = 0; nj < 2; nj++) {
                    uint32_t byte = (b_row + nj * 16) * 128 + (ks * 16 + b_col) * 2;
                    uint32_t swo = sw128(byte);
                    LDSM_X4(bh[nj][0], bh[nj][1], bh[nj][2], bh[nj][3], hbase + swo);
                    LDSM_X4(bl[nj][0], bl[nj][1], bl[nj][2], bl[nj][3], lbase + swo);
                }
#pragma unroll
                for (int mi = 0; mi < 4; mi++) {
#pragma unroll
                    for (int nj = 0; nj < 2; nj++) {
                        MMA16816(acc[mi][nj * 2],     a[mi], bh[nj][0], bh[nj][1]);
                        MMA16816(acc[mi][nj * 2],     a[mi], bl[nj][0], bl[nj][1]);
                        MMA16816(acc[mi][nj * 2 + 1], a[mi], bh[nj][2], bh[nj][3]);
                        MMA16816(acc[mi][nj * 2 + 1], a[mi], bl[nj][2], bl[nj][3]);
                    }
                }
            }
            if (kc + 1 < NKC) encode(kc + 1, (kc + 1) & 1);
            __syncthreads();
        }

        const int row_b = mt * MT + wm * 64 + (lane >> 2);
        const int col_b = nt * 128 + wn * 32 + 2 * (lane & 3);
#pragma unroll
        for (int mi = 0; mi < 4; mi++) {
#pragma unroll
            for (int ni = 0; ni < 4; ni++) {
                int c = col_b + ni * 8;
                int r = row_b + mi * 16;
                float2 v0 = make_float2(acc[mi][ni][0], acc[mi][ni][1]);
                float2 v1 = make_float2(acc[mi][ni][2], acc[mi][ni][3]);
                *(float2*)&g_a1t[(size_t)r * NHP + c] = v0;
                *(float2*)&g_a1t[(size_t)(r + 8) * NHP + c] = v1;
            }
        }
    } else {
        // ------------------ 32-col tail path (cols 384..415) ------------------
        const int wm3 = warp >> 1;    // 0..3, M=32 rows each
        const int wn3 = warp & 1;     // 0..1, N=16 cols each
        const uint32_t a_row = (uint32_t)(wm3 * 32 + (lt & 1) * 8 + lr);
        const uint32_t a_col = (uint32_t)((lt >> 1) * 8);
        const uint32_t b_row = (uint32_t)(wn3 * 16 + (lt >> 1) * 8 + lr);
        const uint32_t b_col = (uint32_t)((lt & 1) * 8);

        for (int kc = 0; kc < NKC; kc++) {
            if (kc + 1 < NKC) issueB(kc + 1, (kc + 1) & 1);
            if (kc + 1 < NKC) {
                asm volatile("cp.async.wait_group 1;" ::: "memory");
            } else {
                asm volatile("cp.async.wait_group 0;" ::: "memory");
            }
            __syncthreads();

            const int buf = kc & 1;
            const uint32_t abase = sb + SA(buf);
            const uint32_t hbase = sb + SBH(buf);
            const uint32_t lbase = sb + SBL(buf);

#pragma unroll
            for (int ks = 0; ks < 4; ks++) {
                uint32_t a[2][4];
#pragma unroll
                for (int mi = 0; mi < 2; mi++) {
                    uint32_t byte = (a_row + mi * 16) * 128 + (ks * 16 + a_col) * 2;
                    LDSM_X4(a[mi][0], a[mi][1], a[mi][2], a[mi][3], abase + sw128(byte));
                }
                uint32_t bh[4], bl[4];
                {
                    uint32_t byte = b_row * 128 + (ks * 16 + b_col) * 2;
                    uint32_t swo = sw128(byte);
                    LDSM_X4(bh[0], bh[1], bh[2], bh[3], hbase + swo);
                    LDSM_X4(bl[0], bl[1], bl[2], bl[3], lbase + swo);
                }
#pragma unroll
                for (int mi = 0; mi < 2; mi++) {
                    MMA16816(acc[mi][0], a[mi], bh[0], bh[1]);
                    MMA16816(acc[mi][0], a[mi], bl[0], bl[1]);
                    MMA16816(acc[mi][1], a[mi], bh[2], bh[3]);
                    MMA16816(acc[mi][1], a[mi], bl[2], bl[3]);
                }
            }
            if (kc + 1 < NKC) encode(kc + 1, (kc + 1) & 1);
            __syncthreads();
        }

        const int row_b = mt * MT + wm3 * 32 + (lane >> 2);
        const int col_b = 384 + wn3 * 16 + 2 * (lane & 3);
#pragma unroll
        for (int mi = 0; mi < 2; mi++) {
#pragma unroll
            for (int ni = 0; ni < 2; ni++) {
                int c = col_b + ni * 8;
                int r = row_b + mi * 16;
                float2 v0 = make_float2(acc[mi][ni][0], acc[mi][ni][1]);
                float2 v1 = make_float2(acc[mi][ni][2], acc[mi][ni][3]);
                *(float2*)&g_a1t[(size_t)r * NHP + c] = v0;
                *(float2*)&g_a1t[(size_t)(r + 8) * NHP + c] = v1;
            }
        }
    }
}

// ---------------------------------------------------------------------------
// Kernel C: PSP FIR (K=64, immediate taps) + threshold on hidden layer.
// ---------------------------------------------------------------------------
#define XROWS 368
#define XP    17

__global__ __launch_bounds__(256) void fir1_kernel() {
    __shared__ float2 xs[XROWS * XP];

    const int tid = threadIdx.x;
    const int n = blockIdx.y;
    const int o0 = blockIdx.x * 32;

    for (int i = tid; i < 64 * XP; i += 256) {
        xs[i] = make_float2(0.0f, 0.0f);
        if (i < 4 * XP) xs[364 * XP + i] = make_float2(0.0f, 0.0f);
    }
    {
        const int j = tid & 7, tr = tid >> 3;
#pragma unroll
        for (int pt = 0; pt < 10; pt++) {
            int t = pt * 32 + tr;
            if (t < TSMP) {
                float4 v = *(const float4*)&g_a1t[((size_t)n * TSMP + t) * NHP + o0 + j * 4];
                xs[(64 + t) * XP + j * 2]     = make_float2(v.x, v.y);
                xs[(64 + t) * XP + j * 2 + 1] = make_float2(v.z, v.w);
            }
        }
    }
    __syncthreads();

    const int w = tid >> 5, lane = tid & 31;
    const int t16 = lane & 15;
    const int osel = lane >> 4;
    const int p = w * 2 + osel;
    const int t0 = t16 * 19;

    float ax[19], ay[19];
#pragma unroll
    for (int j = 0; j < 19; j++) { ax[j] = 0.0f; ay[j] = 0.0f; }

#pragma unroll
    for (int kb = 0; kb < KLEN; kb += 8) {
        float2 rv[26];
        const float2* src = &xs[(64 + t0 + 18 - kb) * XP + p];
#pragma unroll
        for (int r = 0; r < 26; r++) rv[r] = src[-r * XP];
#pragma unroll
        for (int j = 0; j < 19; j++) {
#pragma unroll
            for (int q = 0; q < 8; q++) {
                float2 v = rv[18 - j + q];
                ax[j] += EPS[kb + q] * v.x;
                ay[j] += EPS[kb + q] * v.y;
            }
        }
    }

    const int oa = o0 + 2 * p, ob = oa + 1;
    float* da = &g_s1[((size_t)n * NH + oa) * TSMP + t0];
    float* db = &g_s1[((size_t)n * NH + ob) * TSMP + t0];
    const bool va = (oa < NH), vb = (ob < NH);
#pragma unroll
    for (int j = 0; j < 19; j++) {
        if (t0 + j < TSMP) {
            if (va) da[j] = (ax[j] >= THETA) ? 1.0f : 0.0f;
            if (vb) db[j] = (ay[j] >= THETA) ? 1.0f : 0.0f;
        }
    }
}

// ---------------------------------------------------------------------------
// Kernel D1: fc2 partial GEMM. Grid (hb=4, n).
// ---------------------------------------------------------------------------
#define HSL 104

__global__ __launch_bounds__(320) void fc2a_kernel(const float* __restrict__ W2) {
    __shared__ float W2s[HSL][12];

    const int tid = threadIdx.x;
    const int hb = blockIdx.x;
    const int n = blockIdx.y;
    const int h0 = hb * HSL;
    const int hcnt = (NH - h0 < HSL) ? (NH - h0) : HSL;

    for (int i = tid; i < HSL * 10; i += 320) {
        int hh = i / 10, o = i - hh * 10;
        W2s[hh][o] = (h0 + hh < NH) ? W2[o * NH + h0 + hh] : 0.0f;
    }
    __syncthreads();

    if (tid < TSMP) {
        float acc[NO];
#pragma unroll
        for (int o = 0; o < NO; o++) acc[o] = 0.0f;
        const float* s1n = g_s1 + ((size_t)n * NH + h0) * TSMP + tid;
#pragma unroll 4
        for (int hh = 0; hh < hcnt; hh++) {
            float s = s1n[(size_t)hh * TSMP];
            float4 w0 = *(const float4*)&W2s[hh][0];
            float4 w1 = *(const float4*)&W2s[hh][4];
            float2 w2 = *(const float2*)&W2s[hh][8];
            acc[0] += s * w0.x; acc[1] += s * w0.y;
            acc[2] += s * w0.z; acc[3] += s * w0.w;
            acc[4] += s * w1.x; acc[5] += s * w1.y;
            acc[6] += s * w1.z; acc[7] += s * w1.w;
            acc[8] += s * w2.x; acc[9] += s * w2.y;
        }
        float* dst = g_a2p + (((size_t)hb * NB + n) * NO) * TSMP + tid;
#pragma unroll
        for (int o = 0; o < NO; o++) dst[(size_t)o * TSMP] = acc[o];
    }
}

// ---------------------------------------------------------------------------
// Kernel D2: reduce partials + PSP FIR + threshold. Grid (n).
// ---------------------------------------------------------------------------
#define OFFH 64

__global__ __launch_bounds__(320) void fc2b_kernel(float* __restrict__ out) {
    __shared__ float a2s[NO][OFFH + TSMP];

    const int tid = threadIdx.x;
    const int n = blockIdx.x;

    for (int i = tid; i < NO * OFFH; i += 320) {
        int o = i >> 6;
        a2s[o][i & 63] = 0.0f;
    }
    __syncthreads();

    if (tid < TSMP) {
        const float* src = g_a2p + ((size_t)n * NO) * TSMP + tid;
#pragma unroll
        for (int o = 0; o < NO; o++) {
            float u = src[(size_t)o * TSMP]
                    + src[((size_t)NB * NO + o) * TSMP]
                    + src[((size_t)2 * NB * NO + o) * TSMP]
                    + src[((size_t)3 * NB * NO + o) * TSMP];
            a2s[o][OFFH + tid] = u;
        }
    }
    __syncthreads();

    if (tid < TSMP) {
        const int L = OFFH + tid;
#pragma unroll 1
        for (int o = 0; o < NO; o++) {
            float u = 0.0f;
#pragma unroll
            for (int k = 0; k < KLEN; k++)
                u += EPS[k] * a2s[o][L - k];
            out[((size_t)n * NO + o) * TSMP + tid] = (u >= THETA) ? 1.0f : 0.0f;
        }
    }
}

// ---------------------------------------------------------------------------
extern "C" void kernel_launch(void* const* d_in, const int* in_sizes, int n_in,
                              void* d_out, int out_size) {
    (void)in_sizes; (void)n_in; (void)out_size;
    const float* img = (const float*)d_in[0];   // [128, 784]
    const float* ru  = (const float*)d_in[1];   // [128, 784, 300]
    const float* W1  = (const float*)d_in[2];   // [410, 784]
    const float* W2  = (const float*)d_in[3];   // [10, 410]
    float* out = (float*)d_out;                 // [128, 10, 300]

    split_w_kernel<<<SPLIT_BLOCKS, 256>>>(W1);

    cudaFuncSetAttribute(gemm1_mma_kernel,
                         cudaFuncAttributeMaxDynamicSharedMemorySize, SM_GEMM);
    gemm1_mma_kernel<<<dim3(4, MTILES), 256, SM_GEMM>>>(img, ru);

    fir1_kernel<<<dim3(13, NB), 256>>>();

    fc2a_kernel<<<dim3(4, NB), 320>>>(W2);
    fc2b_kernel<<<NB, 320>>>(out);
}

// round 15
// speedup vs baseline: 1.0864x; 1.0864x over previous
#include <cuda_runtime.h>
#include <cuda_fp16.h>
#include <math.h>
#include <stdint.h>

// ---------------------------------------------------------------------------
// Problem constants
// ---------------------------------------------------------------------------
#define NB    128
#define NI    784
#define NH    410
#define NO    10
#define TSMP  300
#define KLEN  64
#define THETA 10.0f

#define NHP   416               // a1t column stride / B rows (416 = 3*128 + 32)
#define KP    832               // NI padded to 13*64
#define KC    64                // K per chunk
#define NKC   13
#define MT    128               // M rows per CTA
#define GROWS (NB * TSMP)       // 38400
#define MTILES (GROWS / MT)     // 300 exact

// SRM alpha-kernel taps as float literals -> immediate-form FFMA.
__device__ constexpr float EPS[KLEN] = {
    0.0000000000f, 0.2459603111f, 0.4451081857f, 0.6041258122f,
    0.7288475202f, 0.8243606354f, 0.8950948186f, 0.9449011654f,
    0.9771222064f, 0.9946538264f, 1.0000000000f, 0.9953211600f,
    0.9824769037f, 0.9630636870f, 0.9384480644f, 0.9097959895f,
    0.8780986178f, 0.8441950164f, 0.8087921356f, 0.7724823532f,
    0.7357588823f, 0.6990292760f, 0.6626272664f, 0.6268231239f,
    0.5918327133f, 0.5578254003f, 0.5249309464f, 0.4932455146f,
    0.4628368866f, 0.4337489957f, 0.4060058497f, 0.3796149272f,
    0.3545701066f, 0.3308541851f, 0.3084410408f, 0.2872974963f,
    0.2673848822f, 0.2486603977f, 0.2310782389f, 0.2145905593f,
    0.1991482735f, 0.1847017280f, 0.1712012558f, 0.1585976196f,
    0.1468423867f, 0.1358882254f, 0.1256891229f, 0.1162005724f,
    0.1073797042f, 0.0991853624f, 0.0915781944f, 0.0845206424f,
    0.0779770014f, 0.0719133646f, 0.0662976344f, 0.0610994814f,
    0.0562902814f, 0.0518430787f, 0.0477325337f, 0.0439348398f,
    0.0404276820f, 0.0371901540f, 0.0342026963f, 0.0314470440f
};

// ---------------------------------------------------------------------------
// Device scratch (no allocation allowed)
// ---------------------------------------------------------------------------
__device__ __half g_s0[(size_t)GROWS * KP];          // encoded spikes fp16
__device__ __half g_whi[(size_t)NHP * KP];           // W1 fp16 high part
__device__ __half g_wlo[(size_t)NHP * KP];           // W1 fp16 low part
__device__ float  g_a1t[(size_t)GROWS * NHP];        // a1 in [g][o] layout
__device__ float  g_s1[(size_t)NB * NH * TSMP];      // hidden spikes fp32
__device__ float  g_a2p[(size_t)8 * NB * NO * TSMP]; // fc2 partial sums

// ---------------------------------------------------------------------------
// Helpers
// ---------------------------------------------------------------------------
__device__ __forceinline__ uint32_t smem_u32(const void* p) {
    uint32_t a;
    asm("{ .reg .u64 t; cvta.to.shared.u64 t, %1; cvt.u32.u64 %0, t; }"
        : "=r"(a) : "l"(p));
    return a;
}

__device__ __forceinline__ uint32_t sw128(uint32_t byte) {
    return byte ^ ((byte >> 3) & 0x70u);
}

__device__ __forceinline__ void cp_async16(uint32_t dst, const void* src) {
    asm volatile("cp.async.cg.shared.global [%0], [%1], 16;"
                 :: "r"(dst), "l"(src) : "memory");
}
__device__ __forceinline__ void cp_commit() {
    asm volatile("cp.async.commit_group;" ::: "memory");
}

#define LDSM_X4(r0, r1, r2, r3, addr) \
    asm volatile("ldmatrix.sync.aligned.m8n8.x4.shared.b16 {%0,%1,%2,%3}, [%4];" \
                 : "=r"(r0), "=r"(r1), "=r"(r2), "=r"(r3) : "r"(addr))

#define MMA16816(c, a, b0, b1) \
    asm volatile("mma.sync.aligned.m16n8k16.row.col.f32.f16.f16.f32 " \
                 "{%0,%1,%2,%3}, {%4,%5,%6,%7}, {%8,%9}, {%0,%1,%2,%3};" \
                 : "+f"((c)[0]), "+f"((c)[1]), "+f"((c)[2]), "+f"((c)[3]) \
                 : "r"((a)[0]), "r"((a)[1]), "r"((a)[2]), "r"((a)[3]), \
                   "r"(b0), "r"(b1))

// ---------------------------------------------------------------------------
// Kernel A: fused prep — blocks [0,1200) Poisson-encode, rest split W1.
// ---------------------------------------------------------------------------
#define ENC_BLOCKS (GROWS / 32)                      // 1200
#define SPLIT_BLOCKS ((NHP * KP + 255) / 256)        // 1352

__global__ __launch_bounds__(256) void prep_kernel(
    const float* __restrict__ img, const float* __restrict__ ru,
    const float* __restrict__ W1) {
    __shared__ float sm[64][33];
    const int tid = threadIdx.x;

    if (blockIdx.x >= ENC_BLOCKS) {
        int idx = (blockIdx.x - ENC_BLOCKS) * 256 + tid;
        if (idx < NHP * KP) {
            int o = idx / KP;
            int k = idx - o * KP;
            float w = (o < NH && k < NI) ? W1[o * NI + k] : 0.0f;
            __half hi = __float2half_rn(w);
            __half lo = __float2half_rn(w - __half2float(hi));
            g_whi[idx] = hi;
            g_wlo[idx] = lo;
        }
        return;
    }

    const int w = tid >> 5, lane = tid & 31;
    const int g0 = blockIdx.x * 32;
    const int gA = g0 + lane;
    const int nA = gA / TSMP;
    const int tA = gA - nA * TSMP;
    const float* runA = ru + (size_t)nA * NI * TSMP;
    const float* imnA = img + nA * NI;

    for (int ic = 0; ic < NKC; ic++) {
#pragma unroll
        for (int r = 0; r < 8; r++) {
            int i = ic * 64 + w * 8 + r;
            float v = 0.0f;
            if (i < NI) {
                float rv = __ldg(&runA[(size_t)i * TSMP + tA]);
                float im = __ldg(&imnA[i]);
                v = (rv < im) ? 1.0f : 0.0f;
            }
            sm[w * 8 + r][lane] = v;
        }
        __syncthreads();

#pragma unroll
        for (int q = 0; q < 4; q++) {
            int gr = w * 4 + q;
            float lo = sm[2 * lane][gr];
            float hi = sm[2 * lane + 1][gr];
            __half2 h2 = __floats2half2_rn(lo, hi);
            *(__half2*)(g_s0 + (size_t)(g0 + gr) * KP + ic * 64 + 2 * lane) = h2;
        }
        __syncthreads();
    }
}

// ---------------------------------------------------------------------------
// Kernel B: HMMA GEMM  D[g][o] = sum_k s0[g][k] * (Whi[o][k] + Wlo[o][k])
// Grid (nt=4, mt=300): nt<3 -> 128-col tiles, nt==3 -> 32-col tail
// (cols 384..415), eliminating the 96 padding columns of the old 512 layout.
// ---------------------------------------------------------------------------
#define SA(buf)  ((buf) * 16384u)
#define SBH(buf) (32768u + (buf) * 16384u)
#define SBL(buf) (65536u + (buf) * 16384u)
#define SM_GEMM  98304

__global__ __launch_bounds__(256, 2) void gemm1_mma_kernel() {
    extern __shared__ char smem[];
    const uint32_t sb = smem_u32(smem);

    const int tid  = threadIdx.x;
    const int lane = tid & 31;
    const int warp = tid >> 5;
    const int nt   = blockIdx.x;      // 0..3
    const int mt   = blockIdx.y;      // 0..299

    const int lrow = tid >> 3;        // 0..31
    const int lj   = tid & 7;

    auto issue_chunk = [&](int kc, int buf) {
        const __half* srcA = g_s0 + (size_t)(mt * MT) * KP + kc * KC;
#pragma unroll
        for (int it = 0; it < 4; it++) {
            int row = lrow + it * 32;
            uint32_t off = sw128((uint32_t)row * 128 + lj * 16);
            cp_async16(sb + SA(buf) + off, srcA + (size_t)row * KP + lj * 8);
        }
        if (nt < 3) {
            const __half* srcH = g_whi + (size_t)(nt * 128) * KP + kc * KC;
            const __half* srcL = g_wlo + (size_t)(nt * 128) * KP + kc * KC;
#pragma unroll
            for (int it = 0; it < 4; it++) {
                int row = lrow + it * 32;
                uint32_t off = sw128((uint32_t)row * 128 + lj * 16);
                cp_async16(sb + SBH(buf) + off, srcH + (size_t)row * KP + lj * 8);
                cp_async16(sb + SBL(buf) + off, srcL + (size_t)row * KP + lj * 8);
            }
        } else {
            const __half* srcH = g_whi + (size_t)384 * KP + kc * KC;
            const __half* srcL = g_wlo + (size_t)384 * KP + kc * KC;
            int row = lrow;           // 0..31
            uint32_t off = sw128((uint32_t)row * 128 + lj * 16);
            cp_async16(sb + SBH(buf) + off, srcH + (size_t)row * KP + lj * 8);
            cp_async16(sb + SBL(buf) + off, srcL + (size_t)row * KP + lj * 8);
        }
        cp_commit();
    };

    const int lt = lane >> 3;
    const int lr = lane & 7;

    float acc[4][4][4];
#pragma unroll
    for (int i = 0; i < 4; i++)
#pragma unroll
        for (int j = 0; j < 4; j++)
#pragma unroll
            for (int q = 0; q < 4; q++) acc[i][j][q] = 0.0f;

    issue_chunk(0, 0);

    if (nt < 3) {
        // ------------------ full 128-col tile path ------------------
        const int wm = warp >> 2;
        const int wn = warp & 3;
        const uint32_t a_row = (uint32_t)(wm * 64 + (lt & 1) * 8 + lr);
        const uint32_t a_col = (uint32_t)((lt >> 1) * 8);
        const uint32_t b_row = (uint32_t)(wn * 32 + (lt >> 1) * 8 + lr);
        const uint32_t b_col = (uint32_t)((lt & 1) * 8);

        for (int kc = 0; kc < NKC; kc++) {
            if (kc + 1 < NKC) issue_chunk(kc + 1, (kc + 1) & 1);
            if (kc + 1 < NKC) {
                asm volatile("cp.async.wait_group 1;" ::: "memory");
            } else {
                asm volatile("cp.async.wait_group 0;" ::: "memory");
            }
            __syncthreads();

            const int buf = kc & 1;
            const uint32_t abase = sb + SA(buf);
            const uint32_t hbase = sb + SBH(buf);
            const uint32_t lbase = sb + SBL(buf);

#pragma unroll
            for (int ks = 0; ks < 4; ks++) {
                uint32_t a[4][4];
#pragma unroll
                for (int mi = 0; mi < 4; mi++) {
                    uint32_t byte = (a_row + mi * 16) * 128 + (ks * 16 + a_col) * 2;
                    LDSM_X4(a[mi][0], a[mi][1], a[mi][2], a[mi][3], abase + sw128(byte));
                }
                uint32_t bh[2][4], bl[2][4];
#pragma unroll
                for (int nj = 0; nj < 2; nj++) {
                    uint32_t byte = (b_row + nj * 16) * 128 + (ks * 16 + b_col) * 2;
                    uint32_t swo = sw128(byte);
                    LDSM_X4(bh[nj][0], bh[nj][1], bh[nj][2], bh[nj][3], hbase + swo);
                    LDSM_X4(bl[nj][0], bl[nj][1], bl[nj][2], bl[nj][3], lbase + swo);
                }
#pragma unroll
                for (int mi = 0; mi < 4; mi++) {
#pragma unroll
                    for (int nj = 0; nj < 2; nj++) {
                        MMA16816(acc[mi][nj * 2],     a[mi], bh[nj][0], bh[nj][1]);
                        MMA16816(acc[mi][nj * 2],     a[mi], bl[nj][0], bl[nj][1]);
                        MMA16816(acc[mi][nj * 2 + 1], a[mi], bh[nj][2], bh[nj][3]);
                        MMA16816(acc[mi][nj * 2 + 1], a[mi], bl[nj][2], bl[nj][3]);
                    }
                }
            }
            __syncthreads();
        }

        const int row_b = mt * MT + wm * 64 + (lane >> 2);
        const int col_b = nt * 128 + wn * 32 + 2 * (lane & 3);
#pragma unroll
        for (int mi = 0; mi < 4; mi++) {
#pragma unroll
            for (int ni = 0; ni < 4; ni++) {
                int c = col_b + ni * 8;
                int r = row_b + mi * 16;
                float2 v0 = make_float2(acc[mi][ni][0], acc[mi][ni][1]);
                float2 v1 = make_float2(acc[mi][ni][2], acc[mi][ni][3]);
                *(float2*)&g_a1t[(size_t)r * NHP + c] = v0;
                *(float2*)&g_a1t[(size_t)(r + 8) * NHP + c] = v1;
            }
        }
    } else {
        // ------------------ 32-col tail path (cols 384..415) ------------------
        const int wm3 = warp >> 1;    // 0..3, M=32 rows each
        const int wn3 = warp & 1;     // 0..1, N=16 cols each
        const uint32_t a_row = (uint32_t)(wm3 * 32 + (lt & 1) * 8 + lr);
        const uint32_t a_col = (uint32_t)((lt >> 1) * 8);
        const uint32_t b_row = (uint32_t)(wn3 * 16 + (lt >> 1) * 8 + lr);
        const uint32_t b_col = (uint32_t)((lt & 1) * 8);

        for (int kc = 0; kc < NKC; kc++) {
            if (kc + 1 < NKC) issue_chunk(kc + 1, (kc + 1) & 1);
            if (kc + 1 < NKC) {
                asm volatile("cp.async.wait_group 1;" ::: "memory");
            } else {
                asm volatile("cp.async.wait_group 0;" ::: "memory");
            }
            __syncthreads();

            const int buf = kc & 1;
            const uint32_t abase = sb + SA(buf);
            const uint32_t hbase = sb + SBH(buf);
            const uint32_t lbase = sb + SBL(buf);

#pragma unroll
            for (int ks = 0; ks < 4; ks++) {
                uint32_t a[2][4];
#pragma unroll
                for (int mi = 0; mi < 2; mi++) {
                    uint32_t byte = (a_row + mi * 16) * 128 + (ks * 16 + a_col) * 2;
                    LDSM_X4(a[mi][0], a[mi][1], a[mi][2], a[mi][3], abase + sw128(byte));
                }
                uint32_t bh[4], bl[4];
                {
                    uint32_t byte = b_row * 128 + (ks * 16 + b_col) * 2;
                    uint32_t swo = sw128(byte);
                    LDSM_X4(bh[0], bh[1], bh[2], bh[3], hbase + swo);
                    LDSM_X4(bl[0], bl[1], bl[2], bl[3], lbase + swo);
                }
#pragma unroll
                for (int mi = 0; mi < 2; mi++) {
                    MMA16816(acc[mi][0], a[mi], bh[0], bh[1]);
                    MMA16816(acc[mi][0], a[mi], bl[0], bl[1]);
                    MMA16816(acc[mi][1], a[mi], bh[2], bh[3]);
                    MMA16816(acc[mi][1], a[mi], bl[2], bl[3]);
                }
            }
            __syncthreads();
        }

        const int row_b = mt * MT + wm3 * 32 + (lane >> 2);
        const int col_b = 384 + wn3 * 16 + 2 * (lane & 3);
#pragma unroll
        for (int mi = 0; mi < 2; mi++) {
#pragma unroll
            for (int ni = 0; ni < 2; ni++) {
                int c = col_b + ni * 8;
                int r = row_b + mi * 16;
                float2 v0 = make_float2(acc[mi][ni][0], acc[mi][ni][1]);
                float2 v1 = make_float2(acc[mi][ni][2], acc[mi][ni][3]);
                *(float2*)&g_a1t[(size_t)r * NHP + c] = v0;
                *(float2*)&g_a1t[(size_t)(r + 8) * NHP + c] = v1;
            }
        }
    }
}

// ---------------------------------------------------------------------------
// Kernel C: PSP FIR (K=64, immediate taps) + threshold on hidden layer.
// ---------------------------------------------------------------------------
#define XROWS 368
#define XP    17

__global__ __launch_bounds__(256) void fir1_kernel() {
    __shared__ float2 xs[XROWS * XP];

    const int tid = threadIdx.x;
    const int n = blockIdx.y;
    const int o0 = blockIdx.x * 32;

    for (int i = tid; i < 64 * XP; i += 256) {
        xs[i] = make_float2(0.0f, 0.0f);
        if (i < 4 * XP) xs[364 * XP + i] = make_float2(0.0f, 0.0f);
    }
    {
        const int j = tid & 7, tr = tid >> 3;
#pragma unroll
        for (int pt = 0; pt < 10; pt++) {
            int t = pt * 32 + tr;
            if (t < TSMP) {
                float4 v = *(const float4*)&g_a1t[((size_t)n * TSMP + t) * NHP + o0 + j * 4];
                xs[(64 + t) * XP + j * 2]     = make_float2(v.x, v.y);
                xs[(64 + t) * XP + j * 2 + 1] = make_float2(v.z, v.w);
            }
        }
    }
    __syncthreads();

    const int w = tid >> 5, lane = tid & 31;
    const int t16 = lane & 15;
    const int osel = lane >> 4;
    const int p = w * 2 + osel;
    const int t0 = t16 * 19;

    float ax[19], ay[19];
#pragma unroll
    for (int j = 0; j < 19; j++) { ax[j] = 0.0f; ay[j] = 0.0f; }

#pragma unroll
    for (int kb = 0; kb < KLEN; kb += 8) {
        float2 rv[26];
        const float2* src = &xs[(64 + t0 + 18 - kb) * XP + p];
#pragma unroll
        for (int r = 0; r < 26; r++) rv[r] = src[-r * XP];
#pragma unroll
        for (int j = 0; j < 19; j++) {
#pragma unroll
            for (int q = 0; q < 8; q++) {
                float2 v = rv[18 - j + q];
                ax[j] += EPS[kb + q] * v.x;
                ay[j] += EPS[kb + q] * v.y;
            }
        }
    }

    const int oa = o0 + 2 * p, ob = oa + 1;
    float* da = &g_s1[((size_t)n * NH + oa) * TSMP + t0];
    float* db = &g_s1[((size_t)n * NH + ob) * TSMP + t0];
    const bool va = (oa < NH), vb = (ob < NH);
#pragma unroll
    for (int j = 0; j < 19; j++) {
        if (t0 + j < TSMP) {
            if (va) da[j] = (ax[j] >= THETA) ? 1.0f : 0.0f;
            if (vb) db[j] = (ay[j] >= THETA) ? 1.0f : 0.0f;
        }
    }
}

// ---------------------------------------------------------------------------
// Kernel D1: fc2 partial GEMM. Grid (hb=8, n) = 1024 blocks.
// ---------------------------------------------------------------------------
#define HB  8
#define HSL 52

__global__ __launch_bounds__(320) void fc2a_kernel(const float* __restrict__ W2) {
    __shared__ float W2s[HSL][12];

    const int tid = threadIdx.x;
    const int hb = blockIdx.x;
    const int n = blockIdx.y;
    const int h0 = hb * HSL;
    const int hcnt = (NH - h0 < HSL) ? (NH - h0) : HSL;

    for (int i = tid; i < HSL * 10; i += 320) {
        int hh = i / 10, o = i - hh * 10;
        W2s[hh][o] = (h0 + hh < NH) ? W2[o * NH + h0 + hh] : 0.0f;
    }
    __syncthreads();

    if (tid < TSMP) {
        float acc[NO];
#pragma unroll
        for (int o = 0; o < NO; o++) acc[o] = 0.0f;
        const float* s1n = g_s1 + ((size_t)n * NH + h0) * TSMP + tid;
#pragma unroll 4
        for (int hh = 0; hh < hcnt; hh++) {
            float s = s1n[(size_t)hh * TSMP];
            float4 w0 = *(const float4*)&W2s[hh][0];
            float4 w1 = *(const float4*)&W2s[hh][4];
            float2 w2 = *(const float2*)&W2s[hh][8];
            acc[0] += s * w0.x; acc[1] += s * w0.y;
            acc[2] += s * w0.z; acc[3] += s * w0.w;
            acc[4] += s * w1.x; acc[5] += s * w1.y;
            acc[6] += s * w1.z; acc[7] += s * w1.w;
            acc[8] += s * w2.x; acc[9] += s * w2.y;
        }
        float* dst = g_a2p + (((size_t)hb * NB + n) * NO) * TSMP + tid;
#pragma unroll
        for (int o = 0; o < NO; o++) dst[(size_t)o * TSMP] = acc[o];
    }
}

// ---------------------------------------------------------------------------
// Kernel D2: reduce 8 partials + PSP FIR + threshold. Grid (n).
// ---------------------------------------------------------------------------
#define OFFH 64

__global__ __launch_bounds__(320) void fc2b_kernel(float* __restrict__ out) {
    __shared__ float a2s[NO][OFFH + TSMP];

    const int tid = threadIdx.x;
    const int n = blockIdx.x;

    for (int i = tid; i < NO * OFFH; i += 320) {
        int o = i >> 6;
        a2s[o][i & 63] = 0.0f;
    }
    __syncthreads();

    if (tid < TSMP) {
        const float* src = g_a2p + ((size_t)n * NO) * TSMP + tid;
#pragma unroll
        for (int o = 0; o < NO; o++) {
            float u = 0.0f;
#pragma unroll
            for (int hb = 0; hb < HB; hb++)
                u += src[((size_t)hb * NB * NO + o) * TSMP];
            a2s[o][OFFH + tid] = u;
        }
    }
    __syncthreads();

    if (tid < TSMP) {
        const int L = OFFH + tid;
#pragma unroll 1
        for (int o = 0; o < NO; o++) {
            float u = 0.0f;
#pragma unroll
            for (int k = 0; k < KLEN; k++)
                u += EPS[k] * a2s[o][L - k];
            out[((size_t)n * NO + o) * TSMP + tid] = (u >= THETA) ? 1.0f : 0.0f;
        }
    }
}

// ---------------------------------------------------------------------------
extern "C" void kernel_launch(void* const* d_in, const int* in_sizes, int n_in,
                              void* d_out, int out_size) {
    (void)in_sizes; (void)n_in; (void)out_size;
    const float* img = (const float*)d_in[0];   // [128, 784]
    const float* ru  = (const float*)d_in[1];   // [128, 784, 300]
    const float* W1  = (const float*)d_in[2];   // [410, 784]
    const float* W2  = (const float*)d_in[3];   // [10, 410]
    float* out = (float*)d_out;                 // [128, 10, 300]

    prep_kernel<<<ENC_BLOCKS + SPLIT_BLOCKS, 256>>>(img, ru, W1);

    cudaFuncSetAttribute(gemm1_mma_kernel,
                         cudaFuncAttributeMaxDynamicSharedMemorySize, SM_GEMM);
    gemm1_mma_kernel<<<dim3(4, MTILES), 256, SM_GEMM>>>();

    fir1_kernel<<<dim3(13, NB), 256>>>();

    fc2a_kernel<<<dim3(HB, NB), 320>>>(W2);
    fc2b_kernel<<<NB, 320>>>(out);
}